// round 2
// baseline (speedup 1.0000x reference)
#include <cuda_runtime.h>
#include <math.h>

// ---------------------------------------------------------------------------
// SubgraphAttention:
//   q = nve Wq^T + bq ; k = nve Wk^T + bk ; attn = softmax(q k^T/sqrt(D) * mask)
//   members = (attn[:,1:,1:] > 0.05) | I ; greedy sequential clustering;
//   padded expansion out[b,i,0,:]=leader*cls, out[b,i,1+j,:]=member*nve[b,1+j,:]
//
// Algebraic reduction: q_i.k_j = nve_i (Wq^T Wk) nve_j^T + u1[i] + u2[j] + s0
//   C = Wq^T Wk, v1 = Wq^T bk, v2 = Wk^T bq, u1 = nve.v1, u2 = nve.v2, s0=bq.bk
// All math fp32 (threshold 0.05 makes low-precision MMA unsafe). GEMMs use
// packed fma.rn.f32x2 (bit-exact IEEE fp32, 2x FFMA throughput on sm_100a).
// ---------------------------------------------------------------------------

#define BB 32
#define NN 65
#define SS 64
#define DD 512
#define MROWS (BB * NN)   // 2080

static const size_t OUT_ELEMS  = (size_t)BB * SS * NN * DD;    // 68,157,440
static const size_t LEADER_OFF = OUT_ELEMS;
static const size_t MEMBER_OFF = OUT_ELEMS + (size_t)BB * SS;

// ----------------------------- device scratch ------------------------------
__device__ float g_C[DD * DD];
__device__ float g_T[MROWS * DD];
__device__ float g_v1[DD];
__device__ float g_v2[DD];
__device__ float g_s0;
__device__ unsigned long long g_mmask[BB * SS];

// ----------------------------- f32x2 helpers -------------------------------
__device__ __forceinline__ void fma2(unsigned long long& d, unsigned long long a,
                                     unsigned long long b) {
    asm("fma.rn.f32x2 %0, %1, %2, %0;" : "+l"(d) : "l"(a), "l"(b));
}
__device__ __forceinline__ unsigned long long bcast2(float x) {
    unsigned long long r;
    asm("mov.b64 %0, {%1, %1};" : "=l"(r) : "f"(x));
    return r;
}
__device__ __forceinline__ float2 unpk2(unsigned long long v) {
    float2 r;
    asm("mov.b64 {%0, %1}, %2;" : "=f"(r.x), "=f"(r.y) : "l"(v));
    return r;
}

// ----------------------------------------------------------------------------
// prep: v1[d]=sum_n Wq[n,d]*bk[n] ; v2[d]=sum_n Wk[n,d]*bq[n] ; s0=bq.bk
// ----------------------------------------------------------------------------
__global__ __launch_bounds__(512) void prep_kernel(const float* __restrict__ Wq,
                                                   const float* __restrict__ bq,
                                                   const float* __restrict__ Wk,
                                                   const float* __restrict__ bk) {
    __shared__ float sb[512];
    __shared__ float red[512];
    int t = threadIdx.x;
    if (blockIdx.x == 0) {
        sb[t] = bk[t];
        __syncthreads();
        float acc = 0.f;
#pragma unroll 8
        for (int n = 0; n < 512; n++) acc += Wq[n * 512 + t] * sb[n];
        g_v1[t] = acc;
        red[t] = bq[t] * bk[t];
        __syncthreads();
        for (int s = 256; s > 0; s >>= 1) {
            if (t < s) red[t] += red[t + s];
            __syncthreads();
        }
        if (t == 0) g_s0 = red[0];
    } else {
        sb[t] = bq[t];
        __syncthreads();
        float acc = 0.f;
#pragma unroll 8
        for (int n = 0; n < 512; n++) acc += Wk[n * 512 + t] * sb[n];
        g_v2[t] = acc;
    }
}

// ----------------------------------------------------------------------------
// gemm_C: C[m,n] = sum_k Wq[k,m] * Wk[k,n]   (TN, 512x512x512)
// BM=BN=64, BK=32, 256 thr. Thread tile 4M (2tm+32pp) x 4N, f32x2 accumulators.
// ----------------------------------------------------------------------------
__global__ __launch_bounds__(256) void gemm_C_kernel(const float* __restrict__ Wq,
                                                     const float* __restrict__ Wk) {
    __shared__ float As[32][64];
    __shared__ float Bs[32][64];
    const int tid = threadIdx.x;
    const int tm = tid & 15;
    const int tn = tid >> 4;
    const int bm0 = blockIdx.x * 64;
    const int bn0 = blockIdx.y * 64;

    unsigned long long acc[8];
#pragma unroll
    for (int i = 0; i < 8; i++) acc[i] = 0ull;

    float ra[8], rb[8];
#pragma unroll
    for (int it = 0; it < 8; it++) {
        int i = tid + it * 256;
        int r = i >> 6, c = i & 63;
        ra[it] = Wq[r * 512 + bm0 + c];
        rb[it] = Wk[r * 512 + bn0 + c];
    }
#pragma unroll
    for (int it = 0; it < 8; it++) {
        int i = tid + it * 256;
        As[i >> 6][i & 63] = ra[it];
        Bs[i >> 6][i & 63] = rb[it];
    }
    __syncthreads();

    for (int kt = 0; kt < 16; kt++) {
        if (kt < 15) {
            int k0 = (kt + 1) * 32;
#pragma unroll
            for (int it = 0; it < 8; it++) {
                int i = tid + it * 256;
                int r = i >> 6, c = i & 63;
                ra[it] = Wq[(k0 + r) * 512 + bm0 + c];
                rb[it] = Wk[(k0 + r) * 512 + bn0 + c];
            }
        }
#pragma unroll
        for (int k = 0; k < 32; k++) {
            unsigned long long a0 = *reinterpret_cast<const unsigned long long*>(&As[k][2 * tm]);
            unsigned long long a1 = *reinterpret_cast<const unsigned long long*>(&As[k][2 * tm + 32]);
            float4 bv = *reinterpret_cast<const float4*>(&Bs[k][tn * 4]);
            unsigned long long b0 = bcast2(bv.x), b1 = bcast2(bv.y);
            unsigned long long b2 = bcast2(bv.z), b3 = bcast2(bv.w);
            fma2(acc[0], a0, b0); fma2(acc[1], a0, b1);
            fma2(acc[2], a0, b2); fma2(acc[3], a0, b3);
            fma2(acc[4], a1, b0); fma2(acc[5], a1, b1);
            fma2(acc[6], a1, b2); fma2(acc[7], a1, b3);
        }
        __syncthreads();
        if (kt < 15) {
#pragma unroll
            for (int it = 0; it < 8; it++) {
                int i = tid + it * 256;
                As[i >> 6][i & 63] = ra[it];
                Bs[i >> 6][i & 63] = rb[it];
            }
            __syncthreads();
        }
    }
#pragma unroll
    for (int pp = 0; pp < 2; pp++) {
#pragma unroll
        for (int n = 0; n < 4; n++) {
            float2 v = unpk2(acc[pp * 4 + n]);
            int m = bm0 + 2 * tm + 32 * pp;
            int nc = bn0 + tn * 4 + n;
            g_C[m * 512 + nc] = v.x;
            g_C[(m + 1) * 512 + nc] = v.y;
        }
    }
}

// ----------------------------------------------------------------------------
// gemm_T: T[m,n] = sum_k nve[m,k] * C[k,n]  (NN, 2080x512x512)
// BM=128, BN=64, BK=16, 256 thr. Thread tile 8M (2tm+32pp, pp<4) x 4N.
// As transposed [BK][130] (pad keeps 8B align, conflict-free).
// ----------------------------------------------------------------------------
__global__ __launch_bounds__(256) void gemm_T_kernel(const float* __restrict__ nve) {
    __shared__ float As[16][130];
    __shared__ float Bs[16][64];
    const int tid = threadIdx.x;
    const int tm = tid & 15;
    const int tn = tid >> 4;
    const int m0 = blockIdx.x * 128;
    const int n0 = blockIdx.y * 64;

    unsigned long long acc[16];
#pragma unroll
    for (int i = 0; i < 16; i++) acc[i] = 0ull;

    float ra[8], rb[4];
#pragma unroll
    for (int it = 0; it < 8; it++) {
        int i = tid + it * 256;
        int r = i >> 4, c = i & 15;
        int m = m0 + r;
        ra[it] = (m < MROWS) ? nve[m * 512 + c] : 0.f;
    }
#pragma unroll
    for (int it = 0; it < 4; it++) {
        int i = tid + it * 256;
        rb[it] = g_C[(i >> 6) * 512 + n0 + (i & 63)];
    }
#pragma unroll
    for (int it = 0; it < 8; it++) {
        int i = tid + it * 256;
        As[i & 15][i >> 4] = ra[it];
    }
#pragma unroll
    for (int it = 0; it < 4; it++) {
        int i = tid + it * 256;
        Bs[i >> 6][i & 63] = rb[it];
    }
    __syncthreads();

    for (int kt = 0; kt < 32; kt++) {
        if (kt < 31) {
            int k0 = (kt + 1) * 16;
#pragma unroll
            for (int it = 0; it < 8; it++) {
                int i = tid + it * 256;
                int r = i >> 4, c = i & 15;
                int m = m0 + r;
                ra[it] = (m < MROWS) ? nve[m * 512 + k0 + c] : 0.f;
            }
#pragma unroll
            for (int it = 0; it < 4; it++) {
                int i = tid + it * 256;
                rb[it] = g_C[(k0 + (i >> 6)) * 512 + n0 + (i & 63)];
            }
        }
#pragma unroll
        for (int k = 0; k < 16; k++) {
            unsigned long long a[4];
#pragma unroll
            for (int pp = 0; pp < 4; pp++)
                a[pp] = *reinterpret_cast<const unsigned long long*>(&As[k][2 * tm + 32 * pp]);
            float4 bv = *reinterpret_cast<const float4*>(&Bs[k][tn * 4]);
            unsigned long long b0 = bcast2(bv.x), b1 = bcast2(bv.y);
            unsigned long long b2 = bcast2(bv.z), b3 = bcast2(bv.w);
#pragma unroll
            for (int pp = 0; pp < 4; pp++) {
                fma2(acc[pp * 4 + 0], a[pp], b0);
                fma2(acc[pp * 4 + 1], a[pp], b1);
                fma2(acc[pp * 4 + 2], a[pp], b2);
                fma2(acc[pp * 4 + 3], a[pp], b3);
            }
        }
        __syncthreads();
        if (kt < 31) {
#pragma unroll
            for (int it = 0; it < 8; it++) {
                int i = tid + it * 256;
                As[i & 15][i >> 4] = ra[it];
            }
#pragma unroll
            for (int it = 0; it < 4; it++) {
                int i = tid + it * 256;
                Bs[i >> 6][i & 63] = rb[it];
            }
            __syncthreads();
        }
    }
#pragma unroll
    for (int pp = 0; pp < 4; pp++) {
#pragma unroll
        for (int n = 0; n < 4; n++) {
            float2 v = unpk2(acc[pp * 4 + n]);
            int m = m0 + 2 * tm + 32 * pp;
            int nc = n0 + tn * 4 + n;
            if (m < MROWS) g_T[m * 512 + nc] = v.x;
            if (m + 1 < MROWS) g_T[(m + 1) * 512 + nc] = v.y;
        }
    }
}

// ----------------------------------------------------------------------------
// attention + softmax + threshold + greedy clustering (one block per batch)
// ----------------------------------------------------------------------------
static const int ATTN_SMEM = 1040 + (65 * 512 + 512 + 512 + 72 + 72 + 8 * 72) * 4;

__global__ __launch_bounds__(256) void attn_kernel(const float* __restrict__ nve,
                                                   float* __restrict__ out) {
    extern __shared__ char smraw[];
    unsigned long long* s_mask  = (unsigned long long*)smraw;
    unsigned long long* s_final = s_mask + 64;
    unsigned long long* s_leadp = s_final + 64;
    float* s_nve  = (float*)(smraw + 1040);
    float* s_v1   = s_nve + 65 * 512;
    float* s_v2   = s_v1 + 512;
    float* s_u1   = s_v2 + 512;
    float* s_u2   = s_u1 + 72;
    float* s_dots = s_u2 + 72;

    const int b = blockIdx.x;
    const int tid = threadIdx.x;
    const int w = tid >> 5;
    const int lane = tid & 31;
    const unsigned FULL = 0xffffffffu;

    const float4* src = reinterpret_cast<const float4*>(nve + (size_t)b * 65 * 512);
    float4* dstn = reinterpret_cast<float4*>(s_nve);
    for (int i = tid; i < 65 * 128; i += 256) dstn[i] = src[i];
    for (int i = tid; i < 512; i += 256) {
        s_v1[i] = g_v1[i];
        s_v2[i] = g_v2[i];
    }
    __syncthreads();
    const float s0 = g_s0;

    for (int j = w; j < 65; j += 8) {
        float p1 = 0.f, p2 = 0.f;
#pragma unroll
        for (int r = 0; r < 16; r++) {
            float x = s_nve[j * 512 + 32 * r + lane];
            p1 += x * s_v1[32 * r + lane];
            p2 += x * s_v2[32 * r + lane];
        }
        for (int o = 16; o; o >>= 1) {
            p1 += __shfl_xor_sync(FULL, p1, o);
            p2 += __shfl_xor_sync(FULL, p2, o);
        }
        if (lane == 0) { s_u1[j] = p1; s_u2[j] = p2; }
    }
    __syncthreads();

    const float INV_SQRTD = 0.044194173824159216f;  // 1/sqrt(512)

    for (int i = 1 + w; i < 65; i += 8) {
        float t[16];
        const float* Trow = g_T + ((size_t)b * 65 + i) * 512;
#pragma unroll
        for (int r = 0; r < 16; r++) t[r] = Trow[32 * r + lane];
        float* drow = s_dots + w * 72;
        for (int j = 0; j < 65; j++) {
            float acc = 0.f;
#pragma unroll
            for (int r = 0; r < 16; r++) acc += t[r] * s_nve[j * 512 + 32 * r + lane];
            for (int o = 16; o; o >>= 1) acc += __shfl_xor_sync(FULL, acc, o);
            if (lane == 0) {
                drow[j] = (j == i) ? 0.0f
                                   : ((acc + s_u1[i] + s_u2[j] + s0) * INV_SQRTD);
            }
        }
        __syncwarp();
        float v0 = drow[lane];
        float v1 = drow[32 + lane];
        float v2 = (lane == 0) ? drow[64] : -1e30f;
        float mx = fmaxf(v0, fmaxf(v1, v2));
        for (int o = 16; o; o >>= 1) mx = fmaxf(mx, __shfl_xor_sync(FULL, mx, o));
        float e0 = expf(v0 - mx);
        float e1 = expf(v1 - mx);
        float e2 = (lane == 0) ? expf(v2 - mx) : 0.f;
        float sm = e0 + e1 + e2;
        for (int o = 16; o; o >>= 1) sm += __shfl_xor_sync(FULL, sm, o);
        float p0 = e0 / sm, p1 = e1 / sm, p2 = e2 / sm;
        unsigned bal0 = __ballot_sync(FULL, (lane >= 1) && (p0 > 0.05f));
        unsigned bal1 = __ballot_sync(FULL, p1 > 0.05f);
        unsigned bal2 = __ballot_sync(FULL, (lane == 0) && (p2 > 0.05f));
        if (lane == 0) {
            unsigned long long m = ((unsigned long long)(bal0 >> 1)) |
                                   ((unsigned long long)bal1 << 31) |
                                   ((unsigned long long)(bal2 & 1u) << 63);
            m |= 1ull << (i - 1);  // | eye
            s_mask[i - 1] = m;
        }
    }
    __syncthreads();

    if (tid == 0) {
        unsigned long long used = 0ull, lead = 0ull;
        for (int i = 0; i < 64; i++) {
            unsigned long long m = s_mask[i];
            if (!((used >> i) & 1ull)) {
                lead |= 1ull << i;
                used |= m;
                s_final[i] = m;
            } else {
                s_final[i] = 0ull;
            }
        }
        *s_leadp = lead;
    }
    __syncthreads();

    unsigned long long lead = *s_leadp;
    if (tid < 64) {
        out[LEADER_OFF + (size_t)b * 64 + tid] = ((lead >> tid) & 1ull) ? 1.0f : 0.0f;
        g_mmask[b * 64 + tid] = s_final[tid];
    }
    for (int idx = tid; idx < 4096; idx += 256) {
        int i = idx >> 6, j = idx & 63;
        out[MEMBER_OFF + (size_t)b * 4096 + idx] =
            ((s_final[i] >> j) & 1ull) ? 1.0f : 0.0f;
    }
}

// ----------------------------------------------------------------------------
// expansion: out[b,i,0,:]=leader*cls ; out[b,i,1+j,:]=member[b,i,j]*nve[b,1+j,:]
// One block per (b,i); write-bandwidth bound (~273 MB), streaming stores.
// ----------------------------------------------------------------------------
__global__ __launch_bounds__(256) void expand_kernel(const float* __restrict__ nve,
                                                     const float* __restrict__ cls,
                                                     float* __restrict__ out) {
    const int bi = blockIdx.x;
    const int b = bi >> 6;
    const unsigned long long mask = g_mmask[bi];
    const bool lead = (mask != 0ull);   // leader rows always contain eye bit

    const float4* nve4 = reinterpret_cast<const float4*>(nve);
    const float4* cls4 = reinterpret_cast<const float4*>(cls);
    float4* out4 = reinterpret_cast<float4*>(out) + (size_t)bi * 65 * 128;

    const int quad = threadIdx.x & 127;
    const int sub = threadIdx.x >> 7;
    const float4 zero4 = make_float4(0.f, 0.f, 0.f, 0.f);

    for (int r = sub; r < 65; r += 2) {
        float4 v;
        if (r == 0) {
            v = lead ? cls4[quad] : zero4;
        } else {
            v = ((mask >> (r - 1)) & 1ull) ? nve4[((size_t)b * 65 + r) * 128 + quad]
                                           : zero4;
        }
        __stcs(&out4[(size_t)r * 128 + quad], v);
    }
}

// ----------------------------------------------------------------------------
extern "C" void kernel_launch(void* const* d_in, const int* in_sizes, int n_in,
                              void* d_out, int out_size) {
    // inputs: desc_embeddings, name_value_embeddings, Wq, bq, Wk, bk, cls
    const float* nve = (const float*)d_in[1];
    const float* Wq  = (const float*)d_in[2];
    const float* bq  = (const float*)d_in[3];
    const float* Wk  = (const float*)d_in[4];
    const float* bk  = (const float*)d_in[5];
    const float* cls = (const float*)d_in[6];
    float* out = (float*)d_out;

    cudaFuncSetAttribute(attn_kernel, cudaFuncAttributeMaxDynamicSharedMemorySize,
                         ATTN_SMEM);

    prep_kernel<<<2, 512>>>(Wq, bq, Wk, bk);
    gemm_C_kernel<<<dim3(8, 8), 256>>>(Wq, Wk);
    gemm_T_kernel<<<dim3(17, 8), 256>>>(nve);
    attn_kernel<<<BB, 256, ATTN_SMEM>>>(nve, out);
    expand_kernel<<<BB * SS, 256>>>(nve, cls, out);
}

// round 3
// speedup vs baseline: 1.6081x; 1.6081x over previous
#include <cuda_runtime.h>
#include <math.h>

// ---------------------------------------------------------------------------
// SubgraphAttention:
//   q = nve Wq^T + bq ; k = nve Wk^T + bk ; attn = softmax(q k^T/sqrt(D) * mask)
//   members = (attn[:,1:,1:] > 0.05) | I ; greedy sequential clustering;
//   padded expansion out[b,i,0,:]=leader*cls, out[b,i,1+j,:]=member*nve[b,1+j,:]
//
// Algebraic reduction: q_i.k_j = nve_i (Wq^T Wk) nve_j^T + u1[i] + u2[j] + s0
//   C = Wq^T Wk, v1 = Wq^T bk, v2 = Wk^T bq, u1 = nve.v1, u2 = nve.v2, s0=bq.bk
// All math fp32 (threshold 0.05 makes low-precision MMA unsafe). GEMMs use
// packed fma.rn.f32x2 (bit-exact IEEE fp32, 2x FFMA throughput on sm_100a).
// R2 change: attention phase restructured as a register-tiled GEMM (no shuffle
// reductions in the hot loop) + tiny u/cluster kernels.
// ---------------------------------------------------------------------------

#define BB 32
#define NN 65
#define SS 64
#define DD 512
#define MROWS (BB * NN)   // 2080

static const size_t OUT_ELEMS  = (size_t)BB * SS * NN * DD;    // 68,157,440
static const size_t LEADER_OFF = OUT_ELEMS;
static const size_t MEMBER_OFF = OUT_ELEMS + (size_t)BB * SS;

// ----------------------------- device scratch ------------------------------
__device__ float g_C[DD * DD];
__device__ float g_T[MROWS * DD];
__device__ float g_v1[DD];
__device__ float g_v2[DD];
__device__ float g_s0;
__device__ float g_u1[MROWS];
__device__ float g_u2[MROWS];
__device__ unsigned long long g_rawmask[BB * SS];
__device__ unsigned long long g_mmask[BB * SS];

// ----------------------------- f32x2 helpers -------------------------------
__device__ __forceinline__ void fma2(unsigned long long& d, unsigned long long a,
                                     unsigned long long b) {
    asm("fma.rn.f32x2 %0, %1, %2, %0;" : "+l"(d) : "l"(a), "l"(b));
}
__device__ __forceinline__ unsigned long long bcast2(float x) {
    unsigned long long r;
    asm("mov.b64 %0, {%1, %1};" : "=l"(r) : "f"(x));
    return r;
}
__device__ __forceinline__ float2 unpk2(unsigned long long v) {
    float2 r;
    asm("mov.b64 {%0, %1}, %2;" : "=f"(r.x), "=f"(r.y) : "l"(v));
    return r;
}

// ----------------------------------------------------------------------------
// prep: v1[d]=sum_n Wq[n,d]*bk[n] ; v2[d]=sum_n Wk[n,d]*bq[n] ; s0=bq.bk
// ----------------------------------------------------------------------------
__global__ __launch_bounds__(512) void prep_kernel(const float* __restrict__ Wq,
                                                   const float* __restrict__ bq,
                                                   const float* __restrict__ Wk,
                                                   const float* __restrict__ bk) {
    __shared__ float sb[512];
    __shared__ float red[512];
    int t = threadIdx.x;
    if (blockIdx.x == 0) {
        sb[t] = bk[t];
        __syncthreads();
        float acc = 0.f;
#pragma unroll 8
        for (int n = 0; n < 512; n++) acc += Wq[n * 512 + t] * sb[n];
        g_v1[t] = acc;
        red[t] = bq[t] * bk[t];
        __syncthreads();
        for (int s = 256; s > 0; s >>= 1) {
            if (t < s) red[t] += red[t + s];
            __syncthreads();
        }
        if (t == 0) g_s0 = red[0];
    } else {
        sb[t] = bq[t];
        __syncthreads();
        float acc = 0.f;
#pragma unroll 8
        for (int n = 0; n < 512; n++) acc += Wk[n * 512 + t] * sb[n];
        g_v2[t] = acc;
    }
}

// ----------------------------------------------------------------------------
// u_kernel: u1[m] = nve[m,:].v1 ; u2[m] = nve[m,:].v2   (one warp per row)
// ----------------------------------------------------------------------------
__global__ __launch_bounds__(256) void u_kernel(const float* __restrict__ nve) {
    __shared__ float sv1[512], sv2[512];
    const int tid = threadIdx.x;
    for (int i = tid; i < 512; i += 256) {
        sv1[i] = g_v1[i];
        sv2[i] = g_v2[i];
    }
    __syncthreads();
    const int w = tid >> 5, lane = tid & 31;
    const int m = blockIdx.x * 8 + w;
    if (m < MROWS) {
        const float* row = nve + (size_t)m * 512;
        float p1 = 0.f, p2 = 0.f;
#pragma unroll
        for (int r = 0; r < 16; r++) {
            float x = row[r * 32 + lane];
            p1 += x * sv1[r * 32 + lane];
            p2 += x * sv2[r * 32 + lane];
        }
        for (int o = 16; o; o >>= 1) {
            p1 += __shfl_xor_sync(0xffffffffu, p1, o);
            p2 += __shfl_xor_sync(0xffffffffu, p2, o);
        }
        if (lane == 0) { g_u1[m] = p1; g_u2[m] = p2; }
    }
}

// ----------------------------------------------------------------------------
// gemm_C: C[m,n] = sum_k Wq[k,m] * Wk[k,n]   (TN, 512x512x512)
// ----------------------------------------------------------------------------
__global__ __launch_bounds__(256) void gemm_C_kernel(const float* __restrict__ Wq,
                                                     const float* __restrict__ Wk) {
    __shared__ __align__(16) float As[32][64];
    __shared__ __align__(16) float Bs[32][64];
    const int tid = threadIdx.x;
    const int tm = tid & 15;
    const int tn = tid >> 4;
    const int bm0 = blockIdx.x * 64;
    const int bn0 = blockIdx.y * 64;

    unsigned long long acc[8];
#pragma unroll
    for (int i = 0; i < 8; i++) acc[i] = 0ull;

    float ra[8], rb[8];
#pragma unroll
    for (int it = 0; it < 8; it++) {
        int i = tid + it * 256;
        int r = i >> 6, c = i & 63;
        ra[it] = Wq[r * 512 + bm0 + c];
        rb[it] = Wk[r * 512 + bn0 + c];
    }
#pragma unroll
    for (int it = 0; it < 8; it++) {
        int i = tid + it * 256;
        As[i >> 6][i & 63] = ra[it];
        Bs[i >> 6][i & 63] = rb[it];
    }
    __syncthreads();

    for (int kt = 0; kt < 16; kt++) {
        if (kt < 15) {
            int k0 = (kt + 1) * 32;
#pragma unroll
            for (int it = 0; it < 8; it++) {
                int i = tid + it * 256;
                int r = i >> 6, c = i & 63;
                ra[it] = Wq[(k0 + r) * 512 + bm0 + c];
                rb[it] = Wk[(k0 + r) * 512 + bn0 + c];
            }
        }
#pragma unroll
        for (int k = 0; k < 32; k++) {
            unsigned long long a0 = *reinterpret_cast<const unsigned long long*>(&As[k][2 * tm]);
            unsigned long long a1 = *reinterpret_cast<const unsigned long long*>(&As[k][2 * tm + 32]);
            float4 bv = *reinterpret_cast<const float4*>(&Bs[k][tn * 4]);
            unsigned long long b0 = bcast2(bv.x), b1 = bcast2(bv.y);
            unsigned long long b2 = bcast2(bv.z), b3 = bcast2(bv.w);
            fma2(acc[0], a0, b0); fma2(acc[1], a0, b1);
            fma2(acc[2], a0, b2); fma2(acc[3], a0, b3);
            fma2(acc[4], a1, b0); fma2(acc[5], a1, b1);
            fma2(acc[6], a1, b2); fma2(acc[7], a1, b3);
        }
        __syncthreads();
        if (kt < 15) {
#pragma unroll
            for (int it = 0; it < 8; it++) {
                int i = tid + it * 256;
                As[i >> 6][i & 63] = ra[it];
                Bs[i >> 6][i & 63] = rb[it];
            }
            __syncthreads();
        }
    }
#pragma unroll
    for (int pp = 0; pp < 2; pp++) {
#pragma unroll
        for (int n = 0; n < 4; n++) {
            float2 v = unpk2(acc[pp * 4 + n]);
            int m = bm0 + 2 * tm + 32 * pp;
            int nc = bn0 + tn * 4 + n;
            g_C[m * 512 + nc] = v.x;
            g_C[(m + 1) * 512 + nc] = v.y;
        }
    }
}

// ----------------------------------------------------------------------------
// gemm_T: T[m,n] = sum_k nve[m,k] * C[k,n]  (NN, 2080x512x512)
// ----------------------------------------------------------------------------
__global__ __launch_bounds__(256) void gemm_T_kernel(const float* __restrict__ nve) {
    __shared__ __align__(16) float As[16][130];
    __shared__ __align__(16) float Bs[16][64];
    const int tid = threadIdx.x;
    const int tm = tid & 15;
    const int tn = tid >> 4;
    const int m0 = blockIdx.x * 128;
    const int n0 = blockIdx.y * 64;

    unsigned long long acc[16];
#pragma unroll
    for (int i = 0; i < 16; i++) acc[i] = 0ull;

    float ra[8], rb[4];
#pragma unroll
    for (int it = 0; it < 8; it++) {
        int i = tid + it * 256;
        int m = m0 + (i >> 4);
        ra[it] = (m < MROWS) ? nve[m * 512 + (i & 15)] : 0.f;
    }
#pragma unroll
    for (int it = 0; it < 4; it++) {
        int i = tid + it * 256;
        rb[it] = g_C[(i >> 6) * 512 + n0 + (i & 63)];
    }
#pragma unroll
    for (int it = 0; it < 8; it++) {
        int i = tid + it * 256;
        As[i & 15][i >> 4] = ra[it];
    }
#pragma unroll
    for (int it = 0; it < 4; it++) {
        int i = tid + it * 256;
        Bs[i >> 6][i & 63] = rb[it];
    }
    __syncthreads();

    for (int kt = 0; kt < 32; kt++) {
        if (kt < 31) {
            int k0 = (kt + 1) * 16;
#pragma unroll
            for (int it = 0; it < 8; it++) {
                int i = tid + it * 256;
                int m = m0 + (i >> 4);
                ra[it] = (m < MROWS) ? nve[m * 512 + k0 + (i & 15)] : 0.f;
            }
#pragma unroll
            for (int it = 0; it < 4; it++) {
                int i = tid + it * 256;
                rb[it] = g_C[(k0 + (i >> 6)) * 512 + n0 + (i & 63)];
            }
        }
#pragma unroll
        for (int k = 0; k < 16; k++) {
            unsigned long long a[4];
#pragma unroll
            for (int pp = 0; pp < 4; pp++)
                a[pp] = *reinterpret_cast<const unsigned long long*>(&As[k][2 * tm + 32 * pp]);
            float4 bv = *reinterpret_cast<const float4*>(&Bs[k][tn * 4]);
            unsigned long long b0 = bcast2(bv.x), b1 = bcast2(bv.y);
            unsigned long long b2 = bcast2(bv.z), b3 = bcast2(bv.w);
#pragma unroll
            for (int pp = 0; pp < 4; pp++) {
                fma2(acc[pp * 4 + 0], a[pp], b0);
                fma2(acc[pp * 4 + 1], a[pp], b1);
                fma2(acc[pp * 4 + 2], a[pp], b2);
                fma2(acc[pp * 4 + 3], a[pp], b3);
            }
        }
        __syncthreads();
        if (kt < 31) {
#pragma unroll
            for (int it = 0; it < 8; it++) {
                int i = tid + it * 256;
                As[i & 15][i >> 4] = ra[it];
            }
#pragma unroll
            for (int it = 0; it < 4; it++) {
                int i = tid + it * 256;
                Bs[i >> 6][i & 63] = rb[it];
            }
            __syncthreads();
        }
    }
#pragma unroll
    for (int pp = 0; pp < 4; pp++) {
#pragma unroll
        for (int n = 0; n < 4; n++) {
            float2 v = unpk2(acc[pp * 4 + n]);
            int m = m0 + 2 * tm + 32 * pp;
            int nc = n0 + tn * 4 + n;
            if (m < MROWS) g_T[m * 512 + nc] = v.x;
            if (m + 1 < MROWS) g_T[(m + 1) * 512 + nc] = v.y;
        }
    }
}

// ----------------------------------------------------------------------------
// score_kernel: S[i,j] = T[b,i,:].nve[b,j,:] for i in [i0,i0+32), j in [0,65)
// then per-row softmax+threshold -> raw member bitmask. Grid (2, BB).
// Register-tiled f32x2 GEMM: 16x16 threads, 2i x 4j per thread; j=64 column
// accumulated by tn==0 threads. No shuffles in the K loop.
// ----------------------------------------------------------------------------
__global__ __launch_bounds__(256) void score_kernel(const float* __restrict__ nve) {
    __shared__ __align__(16) float As[16][34];   // [k][i] pad->8B-aligned pairs
    __shared__ __align__(16) float Bs[16][68];   // [k][j] 68*4=272B, 16B mult
    __shared__ float sS[32][68];
    __shared__ float su1[32];
    __shared__ float su2[65];

    const int b = blockIdx.y;
    const int i0 = 1 + 32 * blockIdx.x;          // global i of local row 0
    const int tid = threadIdx.x;
    const int tm = tid & 15;
    const int tn = tid >> 4;

    if (tid < 32) su1[tid] = g_u1[b * 65 + i0 + tid];
    else if (tid < 32 + 65) su2[tid - 32] = g_u2[b * 65 + (tid - 32)];

    const float* Tb = g_T + ((size_t)b * 65 + i0) * 512;
    const float* Nb = nve + (size_t)b * 65 * 512;

    unsigned long long acc[4] = {0ull, 0ull, 0ull, 0ull};
    unsigned long long acc64 = 0ull;

    float ra[2], rb[5];
#pragma unroll
    for (int p = 0; p < 2; p++) {
        int i = tid + p * 256;
        ra[p] = Tb[(i >> 4) * 512 + (i & 15)];
    }
#pragma unroll
    for (int p = 0; p < 5; p++) {
        int i = tid + p * 256;
        int j = i >> 4, c = i & 15;
        rb[p] = (i < 1088 && j < 65) ? Nb[j * 512 + c] : 0.f;
    }
#pragma unroll
    for (int p = 0; p < 2; p++) {
        int i = tid + p * 256;
        As[i & 15][i >> 4] = ra[p];
    }
#pragma unroll
    for (int p = 0; p < 5; p++) {
        int i = tid + p * 256;
        if (i < 1088) Bs[i & 15][i >> 4] = rb[p];
    }
    __syncthreads();

    for (int kt = 0; kt < 32; kt++) {
        if (kt < 31) {
            int k0 = (kt + 1) * 16;
#pragma unroll
            for (int p = 0; p < 2; p++) {
                int i = tid + p * 256;
                ra[p] = Tb[(i >> 4) * 512 + k0 + (i & 15)];
            }
#pragma unroll
            for (int p = 0; p < 5; p++) {
                int i = tid + p * 256;
                int j = i >> 4, c = i & 15;
                rb[p] = (i < 1088 && j < 65) ? Nb[j * 512 + k0 + c] : 0.f;
            }
        }
#pragma unroll
        for (int k = 0; k < 16; k++) {
            unsigned long long a = *reinterpret_cast<const unsigned long long*>(&As[k][2 * tm]);
            float4 bv = *reinterpret_cast<const float4*>(&Bs[k][4 * tn]);
            fma2(acc[0], a, bcast2(bv.x));
            fma2(acc[1], a, bcast2(bv.y));
            fma2(acc[2], a, bcast2(bv.z));
            fma2(acc[3], a, bcast2(bv.w));
            if (tn == 0) fma2(acc64, a, bcast2(Bs[k][64]));
        }
        __syncthreads();
        if (kt < 31) {
#pragma unroll
            for (int p = 0; p < 2; p++) {
                int i = tid + p * 256;
                As[i & 15][i >> 4] = ra[p];
            }
#pragma unroll
            for (int p = 0; p < 5; p++) {
                int i = tid + p * 256;
                if (i < 1088) Bs[i & 15][i >> 4] = rb[p];
            }
            __syncthreads();
        }
    }

#pragma unroll
    for (int q = 0; q < 4; q++) {
        float2 v = unpk2(acc[q]);
        sS[2 * tm][4 * tn + q] = v.x;
        sS[2 * tm + 1][4 * tn + q] = v.y;
    }
    if (tn == 0) {
        float2 v = unpk2(acc64);
        sS[2 * tm][64] = v.x;
        sS[2 * tm + 1][64] = v.y;
    }
    __syncthreads();

    // softmax + threshold, 4 rows per warp
    const int w = tid >> 5, lane = tid & 31;
    const unsigned FULL = 0xffffffffu;
    const float INV_SQRTD = 0.044194173824159216f;  // 1/sqrt(512)
    const float s0 = g_s0;
#pragma unroll
    for (int rr = 0; rr < 4; rr++) {
        int r = w * 4 + rr;
        int i = i0 + r;                 // global row (1..64)
        float base = su1[r] + s0;
        int j1 = 32 + lane;
        float L0 = (lane == i) ? 0.f : (sS[r][lane] + base + su2[lane]) * INV_SQRTD;
        float L1 = (j1 == i) ? 0.f : (sS[r][j1] + base + su2[j1]) * INV_SQRTD;
        float L2 = (lane == 0)
                       ? ((i == 64) ? 0.f : (sS[r][64] + base + su2[64]) * INV_SQRTD)
                       : -1e30f;
        float mx = fmaxf(L0, fmaxf(L1, L2));
        for (int o = 16; o; o >>= 1) mx = fmaxf(mx, __shfl_xor_sync(FULL, mx, o));
        float e0 = expf(L0 - mx);
        float e1 = expf(L1 - mx);
        float e2 = (lane == 0) ? expf(L2 - mx) : 0.f;
        float sm = e0 + e1 + e2;
        for (int o = 16; o; o >>= 1) sm += __shfl_xor_sync(FULL, sm, o);
        float inv = 1.0f / sm;
        unsigned bal0 = __ballot_sync(FULL, (lane >= 1) && (e0 * inv > 0.05f));
        unsigned bal1 = __ballot_sync(FULL, e1 * inv > 0.05f);
        unsigned bal2 = __ballot_sync(FULL, (lane == 0) && (e2 * inv > 0.05f));
        if (lane == 0) {
            unsigned long long m = ((unsigned long long)(bal0 >> 1)) |
                                   ((unsigned long long)bal1 << 31) |
                                   ((unsigned long long)(bal2 & 1u) << 63);
            m |= 1ull << (i - 1);  // | eye
            g_rawmask[b * 64 + (i - 1)] = m;
        }
    }
}

// ----------------------------------------------------------------------------
// cluster: greedy sequential clustering per batch + leader/member outputs
// ----------------------------------------------------------------------------
__global__ __launch_bounds__(256) void cluster_kernel(float* __restrict__ out) {
    __shared__ unsigned long long sm[64];
    __shared__ unsigned long long sf[64];
    __shared__ unsigned long long sl;
    const int b = blockIdx.x;
    const int tid = threadIdx.x;
    if (tid < 64) sm[tid] = g_rawmask[b * 64 + tid];
    __syncthreads();
    if (tid == 0) {
        unsigned long long used = 0ull, lead = 0ull;
        for (int i = 0; i < 64; i++) {
            unsigned long long m = sm[i];
            if (!((used >> i) & 1ull)) {
                lead |= 1ull << i;
                used |= m;
                sf[i] = m;
            } else {
                sf[i] = 0ull;
            }
        }
        sl = lead;
    }
    __syncthreads();
    unsigned long long lead = sl;
    if (tid < 64) {
        out[LEADER_OFF + (size_t)b * 64 + tid] = ((lead >> tid) & 1ull) ? 1.0f : 0.0f;
        g_mmask[b * 64 + tid] = sf[tid];
    }
    for (int idx = tid; idx < 4096; idx += 256) {
        out[MEMBER_OFF + (size_t)b * 4096 + idx] =
            ((sf[idx >> 6] >> (idx & 63)) & 1ull) ? 1.0f : 0.0f;
    }
}

// ----------------------------------------------------------------------------
// expansion: out[b,i,0,:]=leader*cls ; out[b,i,1+j,:]=member[b,i,j]*nve[b,1+j,:]
// One block per (b,i); write-bandwidth bound (~273 MB), streaming stores.
// ----------------------------------------------------------------------------
__global__ __launch_bounds__(256) void expand_kernel(const float* __restrict__ nve,
                                                     const float* __restrict__ cls,
                                                     float* __restrict__ out) {
    const int bi = blockIdx.x;
    const int b = bi >> 6;
    const unsigned long long mask = g_mmask[bi];
    const bool lead = (mask != 0ull);   // leader rows always contain eye bit

    const float4* nve4 = reinterpret_cast<const float4*>(nve);
    const float4* cls4 = reinterpret_cast<const float4*>(cls);
    float4* out4 = reinterpret_cast<float4*>(out) + (size_t)bi * 65 * 128;

    const int quad = threadIdx.x & 127;
    const int sub = threadIdx.x >> 7;
    const float4 zero4 = make_float4(0.f, 0.f, 0.f, 0.f);

    for (int r = sub; r < 65; r += 2) {
        float4 v;
        if (r == 0) {
            v = lead ? cls4[quad] : zero4;
        } else {
            v = ((mask >> (r - 1)) & 1ull) ? nve4[((size_t)b * 65 + r) * 128 + quad]
                                           : zero4;
        }
        __stcs(&out4[(size_t)r * 128 + quad], v);
    }
}

// ----------------------------------------------------------------------------
extern "C" void kernel_launch(void* const* d_in, const int* in_sizes, int n_in,
                              void* d_out, int out_size) {
    // inputs: desc_embeddings, name_value_embeddings, Wq, bq, Wk, bk, cls
    const float* nve = (const float*)d_in[1];
    const float* Wq  = (const float*)d_in[2];
    const float* bq  = (const float*)d_in[3];
    const float* Wk  = (const float*)d_in[4];
    const float* bk  = (const float*)d_in[5];
    const float* cls = (const float*)d_in[6];
    float* out = (float*)d_out;

    prep_kernel<<<2, 512>>>(Wq, bq, Wk, bk);
    u_kernel<<<260, 256>>>(nve);
    gemm_C_kernel<<<dim3(8, 8), 256>>>(Wq, Wk);
    gemm_T_kernel<<<dim3(17, 8), 256>>>(nve);
    score_kernel<<<dim3(2, BB), 256>>>(nve);
    cluster_kernel<<<BB, 256>>>(out);
    expand_kernel<<<BB * SS, 256>>>(nve, cls, out);
}